// round 1
// baseline (speedup 1.0000x reference)
#include <cuda_runtime.h>

#define Nn 8192
#define Dd 16
#define Cc 8
#define Rr 64
#define NROWS (Cc + Dd * (Cc + 1))   // 152

__global__ __launch_bounds__(256, 8) void memagg_kernel(
    const float* __restrict__ curr_emb,      // (N, D, R)
    const float* __restrict__ alpha,         // (N, D, 1)
    const float* __restrict__ msg,           // (N, D, R)
    const float* __restrict__ curr_node_mem, // (N, D, C, R)
    const float* __restrict__ curr_rel_mem,  // (N, D, C, R)
    const float* __restrict__ nei_node_mem,  // (N, D, C, R)
    const float* __restrict__ nei_rel_mem,   // (N, D, C, R)
    const float* __restrict__ head_rel_emb,  // (N, D, R)
    const float* __restrict__ head_emb,      // (N, D, R)
    float* __restrict__ out_emb,             // (N, R)
    float* __restrict__ out_node,            // (N, C, R)
    float* __restrict__ out_rel)             // (N, C, R)
{
    const int n    = blockIdx.x;
    const int t    = threadIdx.x;
    const int w    = t >> 5;
    const int lane = t & 31;

    __shared__ __align__(16) float  s_hr[Dd * Rr];   // head_rel_emb[n]
    __shared__ __align__(16) float  s_ne[Rr];        // new_emb[n]
    __shared__ float  s_alpha[Dd];
    __shared__ double s_score[NROWS];
    __shared__ int    s_sel[Cc];

    const size_t baseDR  = (size_t)n * Dd * Rr;
    const size_t baseDCR = (size_t)n * Dd * Cc * Rr;

    if (t < Dd) s_alpha[t] = alpha[(size_t)n * Dd + t];

    // preload head_rel_emb[n] into smem (reused by 144 of 152 score rows)
    for (int i = t; i < Dd * Rr; i += 256) s_hr[i] = head_rel_emb[baseDR + i];
    __syncthreads();

    // new_emb[r] = sum_d alpha[d]*msg[n,d,r] + curr_emb[n,0,r]
    if (t < Rr) {
        float acc = 0.f;
        const float* m = msg + baseDR + t;
        #pragma unroll
        for (int d = 0; d < Dd; d++) acc += s_alpha[d] * m[d * Rr];
        acc += curr_emb[baseDR + t];
        s_ne[t] = acc;
        out_emb[(size_t)n * Rr + t] = acc;
    }
    __syncthreads();

    // ---- scores for 152 rows; fp64 accumulation; each warp does 19 rows ----
    const float2 nev = ((const float2*)s_ne)[lane];

    for (int j = w; j < NROWS; j += 8) {
        float2 a, b;
        if (j < Cc) {
            a = ((const float2*)(curr_node_mem + baseDCR + (size_t)j * Rr))[lane];
            b = ((const float2*)(curr_rel_mem  + baseDCR + (size_t)j * Rr))[lane];
        } else {
            int j2 = j - Cc;
            int d  = j2 / 9;
            int cc = j2 - d * 9;
            float2 h = ((const float2*)(s_hr + d * Rr))[lane];
            if (cc < Cc) {
                a = ((const float2*)(nei_node_mem + baseDCR + (size_t)(d * Cc + cc) * Rr))[lane];
                float2 bb = ((const float2*)(nei_rel_mem + baseDCR + (size_t)(d * Cc + cc) * Rr))[lane];
                b.x = bb.x + h.x;  b.y = bb.y + h.y;
            } else {
                a = ((const float2*)(head_emb + baseDR + (size_t)d * Rr))[lane];
                b = h;
            }
        }
        float dx = (a.x + b.x) - nev.x;
        float dy = (a.y + b.y) - nev.y;
        double s = (double)dx * (double)dx + (double)dy * (double)dy;
        #pragma unroll
        for (int off = 16; off; off >>= 1)
            s += __shfl_down_sync(0xffffffffu, s, off);
        if (lane == 0) s_score[j] = s;
    }
    __syncthreads();

    // ---- top-8 stable selection (max score, tie -> lower index), warp 0 ----
    if (w == 0) {
        for (int k = 0; k < Cc; k++) {
            double bs = -1.0;
            int    bj = NROWS;
            for (int j = lane; j < NROWS; j += 32) {
                double s = s_score[j];
                if (s > bs || (s == bs && j < bj)) { bs = s; bj = j; }
            }
            #pragma unroll
            for (int off = 16; off; off >>= 1) {
                double os = __shfl_down_sync(0xffffffffu, bs, off);
                int    oj = __shfl_down_sync(0xffffffffu, bj, off);
                if (os > bs || (os == bs && oj < bj)) { bs = os; bj = oj; }
            }
            bj = __shfl_sync(0xffffffffu, bj, 0);
            if (lane == 0) { s_sel[k] = bj; s_score[bj] = -2.0; }
            __syncwarp();
        }
    }
    __syncthreads();

    // ---- gather: warp w writes output row (n, w) ----
    // reference does: f = n*C + topkind; row = f/152, col = f%152 (cross-sample!)
    {
        const int jsel = s_sel[w];
        const int f    = n * Cc + jsel;
        const int nn   = f / NROWS;
        const int col  = f - nn * NROWS;
        const size_t gDR  = (size_t)nn * Dd * Rr;
        const size_t gDCR = (size_t)nn * Dd * Cc * Rr;

        float2 a, b;
        if (col < Cc) {
            a = ((const float2*)(curr_node_mem + gDCR + (size_t)col * Rr))[lane];
            b = ((const float2*)(curr_rel_mem  + gDCR + (size_t)col * Rr))[lane];
        } else {
            int c2 = col - Cc;
            int d  = c2 / 9;
            int cc = c2 - d * 9;
            float2 h = ((const float2*)(head_rel_emb + gDR + (size_t)d * Rr))[lane];
            if (cc < Cc) {
                a = ((const float2*)(nei_node_mem + gDCR + (size_t)(d * Cc + cc) * Rr))[lane];
                float2 bb = ((const float2*)(nei_rel_mem + gDCR + (size_t)(d * Cc + cc) * Rr))[lane];
                b.x = bb.x + h.x;  b.y = bb.y + h.y;
            } else {
                a = ((const float2*)(head_emb + gDR + (size_t)d * Rr))[lane];
                b = h;
            }
        }
        ((float2*)(out_node + ((size_t)n * Cc + w) * Rr))[lane] = a;
        ((float2*)(out_rel  + ((size_t)n * Cc + w) * Rr))[lane] = b;
    }
}

extern "C" void kernel_launch(void* const* d_in, const int* in_sizes, int n_in,
                              void* d_out, int out_size)
{
    (void)in_sizes; (void)n_in; (void)out_size;
    const float* curr_emb      = (const float*)d_in[0];
    const float* alpha         = (const float*)d_in[1];
    const float* msg           = (const float*)d_in[2];
    const float* curr_node_mem = (const float*)d_in[3];
    const float* curr_rel_mem  = (const float*)d_in[4];
    const float* nei_node_mem  = (const float*)d_in[5];
    const float* nei_rel_mem   = (const float*)d_in[6];
    const float* head_rel_emb  = (const float*)d_in[7];
    const float* head_emb      = (const float*)d_in[8];

    float* out_emb  = (float*)d_out;                     // N*R
    float* out_node = out_emb  + (size_t)Nn * Rr;        // N*C*R
    float* out_rel  = out_node + (size_t)Nn * Cc * Rr;   // N*C*R

    memagg_kernel<<<Nn, 256>>>(curr_emb, alpha, msg,
                               curr_node_mem, curr_rel_mem,
                               nei_node_mem, nei_rel_mem,
                               head_rel_emb, head_emb,
                               out_emb, out_node, out_rel);
}

// round 2
// speedup vs baseline: 1.5110x; 1.5110x over previous
#include <cuda_runtime.h>

#define Nn 8192
#define Dd 16
#define Cc 8
#define Rr 64
#define NROWS (Cc + Dd * (Cc + 1))   // 152

__global__ __launch_bounds__(256, 4) void memagg_kernel(
    const float* __restrict__ curr_emb,      // (N, D, R)
    const float* __restrict__ alpha,         // (N, D, 1)
    const float* __restrict__ msg,           // (N, D, R)
    const float* __restrict__ curr_node_mem, // (N, D, C, R)
    const float* __restrict__ curr_rel_mem,  // (N, D, C, R)
    const float* __restrict__ nei_node_mem,  // (N, D, C, R)
    const float* __restrict__ nei_rel_mem,   // (N, D, C, R)
    const float* __restrict__ head_rel_emb,  // (N, D, R)
    const float* __restrict__ head_emb,      // (N, D, R)
    float* __restrict__ out_emb,             // (N, R)
    float* __restrict__ out_node,            // (N, C, R)
    float* __restrict__ out_rel)             // (N, C, R)
{
    const int n    = blockIdx.x;
    const int t    = threadIdx.x;
    const int w    = t >> 5;
    const int lane = t & 31;
    const int sub  = lane >> 3;   // 0..3 : row-group within warp
    const int sl   = lane & 7;    // 0..7 : lane within 8-lane group

    __shared__ __align__(16) float  s_hr[Dd * Rr];   // head_rel_emb[n]
    __shared__ __align__(16) float  s_ne[Rr];        // new_emb[n]
    __shared__ float  s_alpha[Dd];
    __shared__ double s_score[NROWS];
    __shared__ int    s_sel[Cc];

    const size_t baseDR  = (size_t)n * Dd * Rr;
    const size_t baseDCR = (size_t)n * Dd * Cc * Rr;

    if (t < Dd) s_alpha[t] = alpha[(size_t)n * Dd + t];

    // head_rel_emb[n]: 1024 floats = 256 x float4, one vector load per thread
    ((float4*)s_hr)[t] = ((const float4*)(head_rel_emb + baseDR))[t];
    __syncthreads();

    // new_emb[r] = sum_d alpha[d]*msg[n,d,r] + curr_emb[n,0,r]
    if (t < Rr) {
        float acc = 0.f;
        const float* m = msg + baseDR + t;
        #pragma unroll
        for (int d = 0; d < Dd; d++) acc += s_alpha[d] * m[d * Rr];
        acc += curr_emb[baseDR + t];
        s_ne[t] = acc;
        out_emb[(size_t)n * Rr + t] = acc;
    }
    __syncthreads();

    // ---- scores for 152 rows ----
    // 4 rows per warp per iteration; 8-lane group per row; 8 floats/lane (2x float4).
    const float4 ne0 = ((const float4*)s_ne)[sl * 2 + 0];
    const float4 ne1 = ((const float4*)s_ne)[sl * 2 + 1];

    #pragma unroll
    for (int i = 0; i < 5; i++) {
        const int  j     = i * 32 + w * 4 + sub;
        const bool valid = (j < NROWS);
        double acc0 = 0.0, acc1 = 0.0;

        if (valid) {
            const float4* pa = nullptr;
            const float4* pb = nullptr;
            const float4* ph = nullptr;
            if (j < Cc) {
                pa = (const float4*)(curr_node_mem + baseDCR + (size_t)j * Rr);
                pb = (const float4*)(curr_rel_mem  + baseDCR + (size_t)j * Rr);
            } else {
                const int j2 = j - Cc;
                const int d  = j2 / 9;
                const int cc = j2 - d * 9;
                ph = (const float4*)(s_hr + d * Rr);
                if (cc < Cc) {
                    pa = (const float4*)(nei_node_mem + baseDCR + (size_t)(d * Cc + cc) * Rr);
                    pb = (const float4*)(nei_rel_mem  + baseDCR + (size_t)(d * Cc + cc) * Rr);
                } else {
                    pa = (const float4*)(head_emb + baseDR + (size_t)d * Rr);
                }
            }
            const float4 a0 = pa[sl * 2 + 0];
            const float4 a1 = pa[sl * 2 + 1];
            float4 b0 = make_float4(0.f, 0.f, 0.f, 0.f);
            float4 b1 = make_float4(0.f, 0.f, 0.f, 0.f);
            if (pb) { b0 = pb[sl * 2 + 0]; b1 = pb[sl * 2 + 1]; }
            float4 h0 = make_float4(0.f, 0.f, 0.f, 0.f);
            float4 h1 = make_float4(0.f, 0.f, 0.f, 0.f);
            if (ph) { h0 = ph[sl * 2 + 0]; h1 = ph[sl * 2 + 1]; }

            // fp32 term order kept identical to R0: (a + (b+h)) - ne
            float dx;
            dx = (a0.x + (b0.x + h0.x)) - ne0.x; acc0 = fma((double)dx, (double)dx, acc0);
            dx = (a0.y + (b0.y + h0.y)) - ne0.y; acc1 = fma((double)dx, (double)dx, acc1);
            dx = (a0.z + (b0.z + h0.z)) - ne0.z; acc0 = fma((double)dx, (double)dx, acc0);
            dx = (a0.w + (b0.w + h0.w)) - ne0.w; acc1 = fma((double)dx, (double)dx, acc1);
            dx = (a1.x + (b1.x + h1.x)) - ne1.x; acc0 = fma((double)dx, (double)dx, acc0);
            dx = (a1.y + (b1.y + h1.y)) - ne1.y; acc1 = fma((double)dx, (double)dx, acc1);
            dx = (a1.z + (b1.z + h1.z)) - ne1.z; acc0 = fma((double)dx, (double)dx, acc0);
            dx = (a1.w + (b1.w + h1.w)) - ne1.w; acc1 = fma((double)dx, (double)dx, acc1);
        }

        double s = acc0 + acc1;
        s += __shfl_down_sync(0xffffffffu, s, 4);
        s += __shfl_down_sync(0xffffffffu, s, 2);
        s += __shfl_down_sync(0xffffffffu, s, 1);
        if (valid && sl == 0) s_score[j] = s;
    }
    __syncthreads();

    // ---- top-8 stable selection (max score, tie -> lower index), warp 0 ----
    if (w == 0) {
        for (int k = 0; k < Cc; k++) {
            double bs = -1.0;
            int    bj = NROWS;
            for (int j = lane; j < NROWS; j += 32) {
                double s = s_score[j];
                if (s > bs || (s == bs && j < bj)) { bs = s; bj = j; }
            }
            #pragma unroll
            for (int off = 16; off; off >>= 1) {
                double os = __shfl_down_sync(0xffffffffu, bs, off);
                int    oj = __shfl_down_sync(0xffffffffu, bj, off);
                if (os > bs || (os == bs && oj < bj)) { bs = os; bj = oj; }
            }
            bj = __shfl_sync(0xffffffffu, bj, 0);
            if (lane == 0) { s_sel[k] = bj; s_score[bj] = -2.0; }
            __syncwarp();
        }
    }
    __syncthreads();

    // ---- gather: warp w writes output row (n, w) ----
    // reference: f = n*C + topkind; row = f/152, col = f%152 (cross-sample)
    {
        const int jsel = s_sel[w];
        const int f    = n * Cc + jsel;
        const int nn   = f / NROWS;
        const int col  = f - nn * NROWS;
        const size_t gDR  = (size_t)nn * Dd * Rr;
        const size_t gDCR = (size_t)nn * Dd * Cc * Rr;

        float2 a, b;
        if (col < Cc) {
            a = ((const float2*)(curr_node_mem + gDCR + (size_t)col * Rr))[lane];
            b = ((const float2*)(curr_rel_mem  + gDCR + (size_t)col * Rr))[lane];
        } else {
            int c2 = col - Cc;
            int d  = c2 / 9;
            int cc = c2 - d * 9;
            float2 h = ((const float2*)(head_rel_emb + gDR + (size_t)d * Rr))[lane];
            if (cc < Cc) {
                a = ((const float2*)(nei_node_mem + gDCR + (size_t)(d * Cc + cc) * Rr))[lane];
                float2 bb = ((const float2*)(nei_rel_mem + gDCR + (size_t)(d * Cc + cc) * Rr))[lane];
                b.x = bb.x + h.x;  b.y = bb.y + h.y;
            } else {
                a = ((const float2*)(head_emb + gDR + (size_t)d * Rr))[lane];
                b = h;
            }
        }
        ((float2*)(out_node + ((size_t)n * Cc + w) * Rr))[lane] = a;
        ((float2*)(out_rel  + ((size_t)n * Cc + w) * Rr))[lane] = b;
    }
}

extern "C" void kernel_launch(void* const* d_in, const int* in_sizes, int n_in,
                              void* d_out, int out_size)
{
    (void)in_sizes; (void)n_in; (void)out_size;
    const float* curr_emb      = (const float*)d_in[0];
    const float* alpha         = (const float*)d_in[1];
    const float* msg           = (const float*)d_in[2];
    const float* curr_node_mem = (const float*)d_in[3];
    const float* curr_rel_mem  = (const float*)d_in[4];
    const float* nei_node_mem  = (const float*)d_in[5];
    const float* nei_rel_mem   = (const float*)d_in[6];
    const float* head_rel_emb  = (const float*)d_in[7];
    const float* head_emb      = (const float*)d_in[8];

    float* out_emb  = (float*)d_out;                     // N*R
    float* out_node = out_emb  + (size_t)Nn * Rr;        // N*C*R
    float* out_rel  = out_node + (size_t)Nn * Cc * Rr;   // N*C*R

    memagg_kernel<<<Nn, 256>>>(curr_emb, alpha, msg,
                               curr_node_mem, curr_rel_mem,
                               nei_node_mem, nei_rel_mem,
                               head_rel_emb, head_emb,
                               out_emb, out_node, out_rel);
}

// round 3
// speedup vs baseline: 1.6229x; 1.0741x over previous
#include <cuda_runtime.h>

#define Nn 8192
#define Dd 16
#define Cc 8
#define Rr 64
#define NROWS (Cc + Dd * (Cc + 1))   // 152

// fp64 score scratch: 8192*152*8B = ~10 MB (static device global, allowed)
__device__ double g_scores[(size_t)Nn * NROWS];

// ---------------------------------------------------------------------------
// Kernel A: new_emb[n,r] = sum_d alpha[n,d]*msg[n,d,r] + curr_emb[n,0,r]
// thread per (n,r); 524288 threads
// ---------------------------------------------------------------------------
__global__ __launch_bounds__(256) void new_emb_kernel(
    const float* __restrict__ msg,
    const float* __restrict__ alpha,
    const float* __restrict__ curr_emb,
    float* __restrict__ out_emb)
{
    const int idx = blockIdx.x * 256 + threadIdx.x;   // 0 .. N*R-1
    const int n = idx >> 6;
    const int r = idx & 63;

    const float* m = msg + (size_t)n * Dd * Rr + r;
    const float* a = alpha + (size_t)n * Dd;

    float acc = 0.f;
    #pragma unroll
    for (int d = 0; d < Dd; d++) acc += a[d] * m[d * Rr];
    acc += curr_emb[(size_t)n * Dd * Rr + r];
    out_emb[idx] = acc;
}

// ---------------------------------------------------------------------------
// Kernel B: score every row (n,j), j in [0,152). Warp = 4 rows, 8-lane groups,
// 8 floats per lane (2x float4). fp64 accumulation. No smem, no barriers.
// ---------------------------------------------------------------------------
__global__ __launch_bounds__(256) void score_kernel(
    const float* __restrict__ curr_node_mem,
    const float* __restrict__ curr_rel_mem,
    const float* __restrict__ nei_node_mem,
    const float* __restrict__ nei_rel_mem,
    const float* __restrict__ head_rel_emb,
    const float* __restrict__ head_emb,
    const float* __restrict__ new_emb)       // out_emb from kernel A
{
    const int gw   = (blockIdx.x * 256 + threadIdx.x) >> 5;  // global warp id
    const int lane = threadIdx.x & 31;
    const int sub  = lane >> 3;
    const int sl   = lane & 7;

    const int row = gw * 4 + sub;            // < Nn*NROWS (exact cover)
    const int n   = row / NROWS;
    const int j   = row - n * NROWS;

    const size_t baseDR  = (size_t)n * Dd * Rr;
    const size_t baseDCR = (size_t)n * Dd * Cc * Rr;

    const float4* pa;
    const float4* pb = nullptr;
    const float4* ph = nullptr;
    if (j < Cc) {
        pa = (const float4*)(curr_node_mem + baseDCR + (size_t)j * Rr);
        pb = (const float4*)(curr_rel_mem  + baseDCR + (size_t)j * Rr);
    } else {
        const int j2 = j - Cc;
        const int d  = j2 / 9;
        const int cc = j2 - d * 9;
        ph = (const float4*)(head_rel_emb + baseDR + (size_t)d * Rr);
        if (cc < Cc) {
            pa = (const float4*)(nei_node_mem + baseDCR + (size_t)(d * Cc + cc) * Rr);
            pb = (const float4*)(nei_rel_mem  + baseDCR + (size_t)(d * Cc + cc) * Rr);
        } else {
            pa = (const float4*)(head_emb + baseDR + (size_t)d * Rr);
        }
    }

    // independent loads: ne(2) + a(2) + b(2) + h(2)
    const float4 ne0 = ((const float4*)(new_emb + (size_t)n * Rr))[sl * 2 + 0];
    const float4 ne1 = ((const float4*)(new_emb + (size_t)n * Rr))[sl * 2 + 1];
    const float4 a0  = pa[sl * 2 + 0];
    const float4 a1  = pa[sl * 2 + 1];
    float4 b0 = make_float4(0.f, 0.f, 0.f, 0.f);
    float4 b1 = make_float4(0.f, 0.f, 0.f, 0.f);
    if (pb) { b0 = pb[sl * 2 + 0]; b1 = pb[sl * 2 + 1]; }
    float4 h0 = make_float4(0.f, 0.f, 0.f, 0.f);
    float4 h1 = make_float4(0.f, 0.f, 0.f, 0.f);
    if (ph) { h0 = ph[sl * 2 + 0]; h1 = ph[sl * 2 + 1]; }

    // fp32 term order identical to prior rounds: (a + (b+h)) - ne
    double acc0 = 0.0, acc1 = 0.0;
    float dx;
    dx = (a0.x + (b0.x + h0.x)) - ne0.x; acc0 = fma((double)dx, (double)dx, acc0);
    dx = (a0.y + (b0.y + h0.y)) - ne0.y; acc1 = fma((double)dx, (double)dx, acc1);
    dx = (a0.z + (b0.z + h0.z)) - ne0.z; acc0 = fma((double)dx, (double)dx, acc0);
    dx = (a0.w + (b0.w + h0.w)) - ne0.w; acc1 = fma((double)dx, (double)dx, acc1);
    dx = (a1.x + (b1.x + h1.x)) - ne1.x; acc0 = fma((double)dx, (double)dx, acc0);
    dx = (a1.y + (b1.y + h1.y)) - ne1.y; acc1 = fma((double)dx, (double)dx, acc1);
    dx = (a1.z + (b1.z + h1.z)) - ne1.z; acc0 = fma((double)dx, (double)dx, acc0);
    dx = (a1.w + (b1.w + h1.w)) - ne1.w; acc1 = fma((double)dx, (double)dx, acc1);

    double s = acc0 + acc1;
    s += __shfl_down_sync(0xffffffffu, s, 4);
    s += __shfl_down_sync(0xffffffffu, s, 2);
    s += __shfl_down_sync(0xffffffffu, s, 1);
    if (sl == 0) g_scores[row] = s;
}

// ---------------------------------------------------------------------------
// Kernel C: per-n topk (stable) + gather. Block per n, 256 threads.
// ---------------------------------------------------------------------------
__global__ __launch_bounds__(256) void topk_gather_kernel(
    const float* __restrict__ curr_node_mem,
    const float* __restrict__ curr_rel_mem,
    const float* __restrict__ nei_node_mem,
    const float* __restrict__ nei_rel_mem,
    const float* __restrict__ head_rel_emb,
    const float* __restrict__ head_emb,
    float* __restrict__ out_node,
    float* __restrict__ out_rel)
{
    const int n    = blockIdx.x;
    const int t    = threadIdx.x;
    const int w    = t >> 5;
    const int lane = t & 31;

    __shared__ double s_score[NROWS];
    __shared__ int    s_sel[Cc];

    if (t < NROWS) s_score[t] = g_scores[(size_t)n * NROWS + t];
    __syncthreads();

    if (w == 0) {
        for (int k = 0; k < Cc; k++) {
            double bs = -1.0;
            int    bj = NROWS;
            for (int j = lane; j < NROWS; j += 32) {
                double s = s_score[j];
                if (s > bs || (s == bs && j < bj)) { bs = s; bj = j; }
            }
            #pragma unroll
            for (int off = 16; off; off >>= 1) {
                double os = __shfl_down_sync(0xffffffffu, bs, off);
                int    oj = __shfl_down_sync(0xffffffffu, bj, off);
                if (os > bs || (os == bs && oj < bj)) { bs = os; bj = oj; }
            }
            bj = __shfl_sync(0xffffffffu, bj, 0);
            if (lane == 0) { s_sel[k] = bj; s_score[bj] = -2.0; }
            __syncwarp();
        }
    }
    __syncthreads();

    // gather: warp w writes output row (n, w)
    // reference: f = n*C + topkind; nn = f/152, col = f%152 (cross-sample)
    const int jsel = s_sel[w];
    const int f    = n * Cc + jsel;
    const int nn   = f / NROWS;
    const int col  = f - nn * NROWS;
    const size_t gDR  = (size_t)nn * Dd * Rr;
    const size_t gDCR = (size_t)nn * Dd * Cc * Rr;

    float2 a, b;
    if (col < Cc) {
        a = ((const float2*)(curr_node_mem + gDCR + (size_t)col * Rr))[lane];
        b = ((const float2*)(curr_rel_mem  + gDCR + (size_t)col * Rr))[lane];
    } else {
        int c2 = col - Cc;
        int d  = c2 / 9;
        int cc = c2 - d * 9;
        float2 h = ((const float2*)(head_rel_emb + gDR + (size_t)d * Rr))[lane];
        if (cc < Cc) {
            a = ((const float2*)(nei_node_mem + gDCR + (size_t)(d * Cc + cc) * Rr))[lane];
            float2 bb = ((const float2*)(nei_rel_mem + gDCR + (size_t)(d * Cc + cc) * Rr))[lane];
            b.x = bb.x + h.x;  b.y = bb.y + h.y;
        } else {
            a = ((const float2*)(head_emb + gDR + (size_t)d * Rr))[lane];
            b = h;
        }
    }
    ((float2*)(out_node + ((size_t)n * Cc + w) * Rr))[lane] = a;
    ((float2*)(out_rel  + ((size_t)n * Cc + w) * Rr))[lane] = b;
}

// ---------------------------------------------------------------------------
extern "C" void kernel_launch(void* const* d_in, const int* in_sizes, int n_in,
                              void* d_out, int out_size)
{
    (void)in_sizes; (void)n_in; (void)out_size;
    const float* curr_emb      = (const float*)d_in[0];
    const float* alpha         = (const float*)d_in[1];
    const float* msg           = (const float*)d_in[2];
    const float* curr_node_mem = (const float*)d_in[3];
    const float* curr_rel_mem  = (const float*)d_in[4];
    const float* nei_node_mem  = (const float*)d_in[5];
    const float* nei_rel_mem   = (const float*)d_in[6];
    const float* head_rel_emb  = (const float*)d_in[7];
    const float* head_emb      = (const float*)d_in[8];

    float* out_emb  = (float*)d_out;                     // N*R
    float* out_node = out_emb  + (size_t)Nn * Rr;        // N*C*R
    float* out_rel  = out_node + (size_t)Nn * Cc * Rr;   // N*C*R

    // A: new_emb  (N*R threads)
    new_emb_kernel<<<(Nn * Rr) / 256, 256>>>(msg, alpha, curr_emb, out_emb);

    // B: scores   (N*NROWS rows, warp = 4 rows, exact cover: 152 = 4*38)
    const int total_warps = (Nn * NROWS) / 4;            // 311296
    score_kernel<<<total_warps / 8, 256>>>(curr_node_mem, curr_rel_mem,
                                           nei_node_mem, nei_rel_mem,
                                           head_rel_emb, head_emb, out_emb);

    // C: topk + gather (block per n)
    topk_gather_kernel<<<Nn, 256>>>(curr_node_mem, curr_rel_mem,
                                    nei_node_mem, nei_rel_mem,
                                    head_rel_emb, head_emb,
                                    out_node, out_rel);
}

// round 4
// speedup vs baseline: 3.7514x; 2.3115x over previous
#include <cuda_runtime.h>

#define Nn 8192
#define Dd 16
#define Cc 8
#define Rr 64
#define NROWS (Cc + Dd * (Cc + 1))   // 152

// fp64 score scratch: 8192*152*8B = ~10 MB (static device global, allowed)
__device__ double g_scores[(size_t)Nn * NROWS];

// ---------------------------------------------------------------------------
// Kernel A: new_emb[n,r] = sum_d alpha[n,d]*msg[n,d,r] + curr_emb[n,0,r]
// ---------------------------------------------------------------------------
__global__ __launch_bounds__(256) void new_emb_kernel(
    const float* __restrict__ msg,
    const float* __restrict__ alpha,
    const float* __restrict__ curr_emb,
    float* __restrict__ out_emb)
{
    const int idx = blockIdx.x * 256 + threadIdx.x;   // 0 .. N*R-1
    const int n = idx >> 6;
    const int r = idx & 63;

    const float* m = msg + (size_t)n * Dd * Rr + r;
    const float* a = alpha + (size_t)n * Dd;

    float acc = 0.f;
    #pragma unroll
    for (int d = 0; d < Dd; d++) acc += a[d] * m[d * Rr];
    acc += curr_emb[(size_t)n * Dd * Rr + r];
    out_emb[idx] = acc;
}

// ---------------------------------------------------------------------------
// Kernel B: score every row (n,j). Warp = 4 rows, 8-lane groups, 8 floats/lane.
// fp32 per-lane pairwise tree; fp64 only for the exact 8-lane combine.
// ---------------------------------------------------------------------------
__global__ __launch_bounds__(256) void score_kernel(
    const float* __restrict__ curr_node_mem,
    const float* __restrict__ curr_rel_mem,
    const float* __restrict__ nei_node_mem,
    const float* __restrict__ nei_rel_mem,
    const float* __restrict__ head_rel_emb,
    const float* __restrict__ head_emb,
    const float* __restrict__ new_emb)
{
    const int gw   = (blockIdx.x * 256 + threadIdx.x) >> 5;
    const int lane = threadIdx.x & 31;
    const int sub  = lane >> 3;
    const int sl   = lane & 7;

    const int row = gw * 4 + sub;            // exact cover: 152 % 4 == 0
    const int n   = row / NROWS;
    const int j   = row - n * NROWS;

    const size_t baseDR  = (size_t)n * Dd * Rr;
    const size_t baseDCR = (size_t)n * Dd * Cc * Rr;

    const float4* pa;
    const float4* pb = nullptr;
    const float4* ph = nullptr;
    if (j < Cc) {
        pa = (const float4*)(curr_node_mem + baseDCR + (size_t)j * Rr);
        pb = (const float4*)(curr_rel_mem  + baseDCR + (size_t)j * Rr);
    } else {
        const int j2 = j - Cc;
        const int d  = j2 / 9;
        const int cc = j2 - d * 9;
        ph = (const float4*)(head_rel_emb + baseDR + (size_t)d * Rr);
        if (cc < Cc) {
            pa = (const float4*)(nei_node_mem + baseDCR + (size_t)(d * Cc + cc) * Rr);
            pb = (const float4*)(nei_rel_mem  + baseDCR + (size_t)(d * Cc + cc) * Rr);
        } else {
            pa = (const float4*)(head_emb + baseDR + (size_t)d * Rr);
        }
    }

    const float4 ne0 = ((const float4*)(new_emb + (size_t)n * Rr))[sl * 2 + 0];
    const float4 ne1 = ((const float4*)(new_emb + (size_t)n * Rr))[sl * 2 + 1];
    const float4 a0  = pa[sl * 2 + 0];
    const float4 a1  = pa[sl * 2 + 1];
    float4 b0 = make_float4(0.f, 0.f, 0.f, 0.f);
    float4 b1 = make_float4(0.f, 0.f, 0.f, 0.f);
    if (pb) { b0 = pb[sl * 2 + 0]; b1 = pb[sl * 2 + 1]; }
    float4 h0 = make_float4(0.f, 0.f, 0.f, 0.f);
    float4 h1 = make_float4(0.f, 0.f, 0.f, 0.f);
    if (ph) { h0 = ph[sl * 2 + 0]; h1 = ph[sl * 2 + 1]; }

    // fp32 term order identical to prior rounds: (a + (b+h)) - ne
    float d0 = (a0.x + (b0.x + h0.x)) - ne0.x;
    float d1 = (a0.y + (b0.y + h0.y)) - ne0.y;
    float d2 = (a0.z + (b0.z + h0.z)) - ne0.z;
    float d3 = (a0.w + (b0.w + h0.w)) - ne0.w;
    float d4 = (a1.x + (b1.x + h1.x)) - ne1.x;
    float d5 = (a1.y + (b1.y + h1.y)) - ne1.y;
    float d6 = (a1.z + (b1.z + h1.z)) - ne1.z;
    float d7 = (a1.w + (b1.w + h1.w)) - ne1.w;

    // fp32 pairwise tree of squares (error ~2 ulp of partial)
    float q0 = fmaf(d0, d0, d1 * d1);
    float q1 = fmaf(d2, d2, d3 * d3);
    float q2 = fmaf(d4, d4, d5 * d5);
    float q3 = fmaf(d6, d6, d7 * d7);
    float part = (q0 + q1) + (q2 + q3);

    // exact fp64 combine across the 8-lane group
    double s = (double)part;
    s += __shfl_down_sync(0xffffffffu, s, 4);
    s += __shfl_down_sync(0xffffffffu, s, 2);
    s += __shfl_down_sync(0xffffffffu, s, 1);
    if (sl == 0) g_scores[row] = s;
}

// ---------------------------------------------------------------------------
// Kernel C: per-n topk (stable) + gather. Block per n, 256 threads.
// ---------------------------------------------------------------------------
__global__ __launch_bounds__(256) void topk_gather_kernel(
    const float* __restrict__ curr_node_mem,
    const float* __restrict__ curr_rel_mem,
    const float* __restrict__ nei_node_mem,
    const float* __restrict__ nei_rel_mem,
    const float* __restrict__ head_rel_emb,
    const float* __restrict__ head_emb,
    float* __restrict__ out_node,
    float* __restrict__ out_rel)
{
    const int n    = blockIdx.x;
    const int t    = threadIdx.x;
    const int w    = t >> 5;
    const int lane = t & 31;

    __shared__ double s_score[NROWS];
    __shared__ int    s_sel[Cc];

    if (t < NROWS) s_score[t] = g_scores[(size_t)n * NROWS + t];
    __syncthreads();

    if (w == 0) {
        for (int k = 0; k < Cc; k++) {
            double bs = -1.0;
            int    bj = NROWS;
            for (int j = lane; j < NROWS; j += 32) {
                double s = s_score[j];
                if (s > bs || (s == bs && j < bj)) { bs = s; bj = j; }
            }
            #pragma unroll
            for (int off = 16; off; off >>= 1) {
                double os = __shfl_down_sync(0xffffffffu, bs, off);
                int    oj = __shfl_down_sync(0xffffffffu, bj, off);
                if (os > bs || (os == bs && oj < bj)) { bs = os; bj = oj; }
            }
            bj = __shfl_sync(0xffffffffu, bj, 0);
            if (lane == 0) { s_sel[k] = bj; s_score[bj] = -2.0; }
            __syncwarp();
        }
    }
    __syncthreads();

    // gather: warp w writes output row (n, w)
    // reference: f = n*C + topkind; nn = f/152, col = f%152 (cross-sample)
    const int jsel = s_sel[w];
    const int f    = n * Cc + jsel;
    const int nn   = f / NROWS;
    const int col  = f - nn * NROWS;
    const size_t gDR  = (size_t)nn * Dd * Rr;
    const size_t gDCR = (size_t)nn * Dd * Cc * Rr;

    float2 a, b;
    if (col < Cc) {
        a = ((const float2*)(curr_node_mem + gDCR + (size_t)col * Rr))[lane];
        b = ((const float2*)(curr_rel_mem  + gDCR + (size_t)col * Rr))[lane];
    } else {
        int c2 = col - Cc;
        int d  = c2 / 9;
        int cc = c2 - d * 9;
        float2 h = ((const float2*)(head_rel_emb + gDR + (size_t)d * Rr))[lane];
        if (cc < Cc) {
            a = ((const float2*)(nei_node_mem + gDCR + (size_t)(d * Cc + cc) * Rr))[lane];
            float2 bb = ((const float2*)(nei_rel_mem + gDCR + (size_t)(d * Cc + cc) * Rr))[lane];
            b.x = bb.x + h.x;  b.y = bb.y + h.y;
        } else {
            a = ((const float2*)(head_emb + gDR + (size_t)d * Rr))[lane];
            b = h;
        }
    }
    ((float2*)(out_node + ((size_t)n * Cc + w) * Rr))[lane] = a;
    ((float2*)(out_rel  + ((size_t)n * Cc + w) * Rr))[lane] = b;
}

// ---------------------------------------------------------------------------
extern "C" void kernel_launch(void* const* d_in, const int* in_sizes, int n_in,
                              void* d_out, int out_size)
{
    (void)in_sizes; (void)n_in; (void)out_size;
    const float* curr_emb      = (const float*)d_in[0];
    const float* alpha         = (const float*)d_in[1];
    const float* msg           = (const float*)d_in[2];
    const float* curr_node_mem = (const float*)d_in[3];
    const float* curr_rel_mem  = (const float*)d_in[4];
    const float* nei_node_mem  = (const float*)d_in[5];
    const float* nei_rel_mem   = (const float*)d_in[6];
    const float* head_rel_emb  = (const float*)d_in[7];
    const float* head_emb      = (const float*)d_in[8];

    float* out_emb  = (float*)d_out;                     // N*R
    float* out_node = out_emb  + (size_t)Nn * Rr;        // N*C*R
    float* out_rel  = out_node + (size_t)Nn * Cc * Rr;   // N*C*R

    // A: new_emb
    new_emb_kernel<<<(Nn * Rr) / 256, 256>>>(msg, alpha, curr_emb, out_emb);

    // B: scores (warp = 4 rows; exact cover)
    const int total_warps = (Nn * NROWS) / 4;            // 311296
    score_kernel<<<total_warps / 8, 256>>>(curr_node_mem, curr_rel_mem,
                                           nei_node_mem, nei_rel_mem,
                                           head_rel_emb, head_emb, out_emb);

    // C: topk + gather
    topk_gather_kernel<<<Nn, 256>>>(curr_node_mem, curr_rel_mem,
                                    nei_node_mem, nei_rel_mem,
                                    head_rel_emb, head_emb,
                                    out_node, out_rel);
}